// round 17
// baseline (speedup 1.0000x reference)
#include <cuda_runtime.h>
#include <cuda_fp16.h>
#include <cstdint>

#define NTOK 49
#define CDIM 128
#define THREADS 512

// ---- persistent prepped buffers ----
__device__ __align__(16) __half g_wall[4 * 128 * 136];   // fp16 [ch][j][136]: qkv0,1,2,proj; q-scale folded
__device__ float g_qkvb[512];                            // fp32 biases (q scaled) ++ proj_b
__device__ float g_bm[64 * 4 * 49 * 56];                 // fused rel-pos bias + mask

// ---- smem byte map (1 CTA/SM, persistent) ----
#define O_W   0        // 4 x [128][136]h weights = 139264
#define O_XS  139264   // [64][136]h x/o tile     = 17408
#define O_K   156672   // [4][56][40]h            = 17920
#define O_V   174592   // [4][64][40]h V row-major (rows 56..63 ZERO) = 20480
#define O_SCR 195072   // [49][128]f32 raw x      = 25088
#define O_SB  220160   // 512 f32 biases          = 2048
#define SMEM_BYTES 222208

#define WSTR 136       // halfs
#define CHH  17408     // halfs per weight chunk
#define QSTR 40
#define KHSZ (56 * QSTR)
#define VHSZ (64 * QSTR)   // V: 64 token rows (56..63 zero), 40-half stride

__device__ __forceinline__ void stu(__half* p, uint32_t v) {
    *reinterpret_cast<uint32_t*>(p) = v;
}
__device__ __forceinline__ uint32_t pack2(float a, float b) {
    __half2 h = __floats2half2_rn(a, b);
    return *reinterpret_cast<uint32_t*>(&h);
}
__device__ __forceinline__ void mma16(float c[4], const uint32_t a[4],
                                      uint32_t b0, uint32_t b1) {
    asm volatile(
        "mma.sync.aligned.m16n8k16.row.col.f32.f16.f16.f32 "
        "{%0,%1,%2,%3},{%4,%5,%6,%7},{%8,%9},{%0,%1,%2,%3};\n"
        : "+f"(c[0]), "+f"(c[1]), "+f"(c[2]), "+f"(c[3])
        : "r"(a[0]), "r"(a[1]), "r"(a[2]), "r"(a[3]), "r"(b0), "r"(b1));
}
__device__ __forceinline__ uint32_t smem_u32(const void* p) {
    return (uint32_t)__cvta_generic_to_shared(p);
}
__device__ __forceinline__ void ldsm4(uint32_t r[4], uint32_t addr) {
    asm volatile("ldmatrix.sync.aligned.m8n8.x4.shared.b16 {%0,%1,%2,%3}, [%4];"
        : "=r"(r[0]), "=r"(r[1]), "=r"(r[2]), "=r"(r[3]) : "r"(addr));
}
__device__ __forceinline__ void ldsm4t(uint32_t r[4], uint32_t addr) {
    asm volatile("ldmatrix.sync.aligned.m8n8.x4.trans.shared.b16 {%0,%1,%2,%3}, [%4];"
        : "=r"(r[0]), "=r"(r[1]), "=r"(r[2]), "=r"(r[3]) : "r"(addr));
}
__device__ __forceinline__ void ldsm2(uint32_t r[2], uint32_t addr) {
    asm volatile("ldmatrix.sync.aligned.m8n8.x2.shared.b16 {%0,%1}, [%2];"
        : "=r"(r[0]), "=r"(r[1]) : "r"(addr));
}
__device__ __forceinline__ void cp16(uint32_t dst, const void* src) {
    asm volatile("cp.async.cg.shared.global [%0], [%1], 16;\n" :: "r"(dst), "l"(src) : "memory");
}
#define CP_COMMIT asm volatile("cp.async.commit_group;\n" ::: "memory")
#define CP_WAIT0  asm volatile("cp.async.wait_group 0;\n" ::: "memory")

// ================= merged prep kernel =================
#define BM_N (64 * 4 * 49 * 56)
__global__ void prep_all(const float* __restrict__ qkv_w, const float* __restrict__ qkv_b,
                         const float* __restrict__ proj_w, const float* __restrict__ proj_b,
                         const float* __restrict__ mask, const float* __restrict__ bias_table)
{
    int idx = blockIdx.x * 256 + threadIdx.x;
    const float scale = 0.17677669529663687f;   // 32^-0.5
    if (idx < BM_N) {
        int j = idx % 56;
        int rest = idx / 56;
        int i = rest % 49; rest /= 49;
        int h = rest & 3;
        int w = rest >> 2;
        float v = 0.f;
        if (j < 49) {
            int ih = i / 7, iw = i - 7 * ih;
            int jh = j / 7, jw = j - 7 * jh;
            int ridx = (ih - jh + 6) * 13 + (iw - jw + 6);
            v = bias_table[ridx * 4 + h] + mask[(size_t)(w * 49 + i) * 49 + j];
        }
        g_bm[idx] = v;
        return;
    }
    idx -= BM_N;
    if (idx < 49152) {
        int ch = idx >> 14;
        int j  = (idx >> 7) & 127;
        int k  = idx & 127;
        float v = qkv_w[(size_t)(ch * 128 + j) * 128 + k];
        if (ch == 0) v *= scale;
        g_wall[ch * CHH + j * WSTR + k] = __float2half_rn(v);
    } else if (idx < 65536) {
        int i2 = idx - 49152;
        int j = i2 >> 7, k = i2 & 127;
        g_wall[3 * CHH + j * WSTR + k] = __float2half_rn(proj_w[(size_t)j * 128 + k]);
    } else if (idx < 65536 + 384) {
        int i = idx - 65536;
        float v = qkv_b[i];
        if (i < 128) v *= scale;
        g_qkvb[i] = v;
    } else if (idx < 65536 + 512) {
        int i = idx - 65536;
        g_qkvb[i] = proj_b[i - 384];
    }
}

// ================= persistent main kernel =================
__global__ __launch_bounds__(THREADS, 1)
void wattn(const float* __restrict__ x, float* __restrict__ out, int NW)
{
    extern __shared__ char smem[];
    __half* ws  = (__half*)(smem + O_W);
    __half* xs  = (__half*)(smem + O_XS);
    __half* kb  = (__half*)(smem + O_K);
    __half* vb  = (__half*)(smem + O_V);
    float*  scr = (float*)(smem + O_SCR);
    float*  sb  = (float*)(smem + O_SB);

    const int tid  = threadIdx.x;
    const int wid  = tid >> 5;
    const int lane = tid & 31;
    const int g    = lane >> 2;
    const int t    = lane & 3;

    const int lrA = (lane & 7) + (lane & 8);
    const int lkA = (lane & 16) ? 8 : 0;
    const int lrB = (lane & 7) + ((lane >> 1) & 8);
    const int lkB = lane & 8;

    const uint32_t sm32 = smem_u32(smem);

    // ---- prologue: stage ALL weights once; first x; zero V; biases ----
#pragma unroll
    for (int i = 0; i < 17; i++) {
        int idx = tid + i * THREADS;          // 0..8703 (x16B = 139264 B)
        cp16(sm32 + O_W + idx * 16, (const char*)g_wall + idx * 16);
    }
    {
        const char* xsrc = (const char*)(x + (size_t)blockIdx.x * (NTOK * CDIM));
#pragma unroll
        for (int i = 0; i < 4; i++) {
            int idx = tid + i * THREADS;
            if (idx < 1568) cp16(sm32 + O_SCR + idx * 16, xsrc + idx * 16);
        }
    }
    CP_COMMIT;
    // zero V region ONCE (rows 56..63 stay zero forever; Phase B only writes 0..55)
    {
#pragma unroll
        for (int i = 0; i < 3; i++) {
            int idx = tid + i * THREADS;      // 0..1279 (x16B = 20480 B)
            if (idx < 1280)
                asm volatile("st.shared.v4.b32 [%0], {%1,%1,%1,%1};"
                    :: "r"(sm32 + O_V + idx * 16), "r"(0) : "memory");
        }
    }
    sb[tid] = g_qkvb[tid];

    const int mi = wid & 3;       // 16-row block
    const int nq = wid >> 2;      // 32-col block == head
    const uint32_t aX  = smem_u32(xs + (mi * 16 + lrA) * WSTR + lkA);
    const uint32_t bW  = smem_u32(ws + (nq * 32 + lrB) * WSTR + lkB);
    const int r0 = mi * 16 + g;

    for (int w = blockIdx.x; w < NW; w += gridDim.x) {
        CP_WAIT0;
        __syncthreads();

        // ---- Phase A: scratch fp32 -> xs fp16 [64][136] via STS.128 ----
#pragma unroll
        for (int it = 0; it < 2; it++) {
            int i = tid + it * THREADS;       // 0..1023
            int r = i >> 4, c16 = i & 15;     // 16B column group (8 halfs)
            float4 v0, v1;
            if (r < NTOK) {
                v0 = ((const float4*)scr)[r * 32 + c16 * 2];
                v1 = ((const float4*)scr)[r * 32 + c16 * 2 + 1];
            } else {
                v0 = make_float4(0.f, 0.f, 0.f, 0.f); v1 = v0;
            }
            uint32_t p0 = pack2(v0.x, v0.y), p1 = pack2(v0.z, v0.w);
            uint32_t p2 = pack2(v1.x, v1.y), p3 = pack2(v1.z, v1.w);
            asm volatile("st.shared.v4.b32 [%0], {%1,%2,%3,%4};"
                :: "r"(sm32 + O_XS + (r * WSTR + c16 * 8) * 2),
                   "r"(p0), "r"(p1), "r"(p2), "r"(p3) : "memory");
        }
        // prefetch next window's x (per-thread idx ownership == phase-A reads)
        {
            int wn = w + gridDim.x;
            if (wn < NW) {
                const char* xsrc = (const char*)(x + (size_t)wn * (NTOK * CDIM));
#pragma unroll
                for (int i2 = 0; i2 < 4; i2++) {
                    int idx = tid + i2 * THREADS;
                    if (idx < 1568) cp16(sm32 + O_SCR + idx * 16, xsrc + idx * 16);
                }
            }
            CP_COMMIT;
        }
        __syncthreads();

        // ---- Phase B: QKV (3 chunks, resident weights) ----
        uint32_t qa[2][4];
#pragma unroll
        for (int ch = 0; ch < 3; ch++) {
            float acc[4][4];
#pragma unroll
            for (int i = 0; i < 4; i++)
#pragma unroll
                for (int j = 0; j < 4; j++) acc[i][j] = 0.f;

            const uint32_t bC0 = bW + ch * (CHH * 2);
            const uint32_t bC1 = bC0 + 16 * WSTR * 2;
#pragma unroll
            for (int ks = 0; ks < 8; ks++) {
                uint32_t a0[4], q0[4], q1[4];
                ldsm4(a0, aX + ks * 32);
                ldsm4(q0, bC0 + ks * 32);
                ldsm4(q1, bC1 + ks * 32);
                mma16(acc[0], a0, q0[0], q0[1]);
                mma16(acc[1], a0, q0[2], q0[3]);
                mma16(acc[2], a0, q1[0], q1[1]);
                mma16(acc[3], a0, q1[2], q1[3]);
            }

            const float* bch = sb + ch * 128;
#pragma unroll
            for (int nt = 0; nt < 4; nt++) {
                const int c0 = nq * 32 + nt * 8 + 2 * t;
                const int d0 = nt * 8 + 2 * t;
                float v0 = acc[nt][0] + bch[c0];
                float v1 = acc[nt][1] + bch[c0 + 1];
                float v2 = acc[nt][2] + bch[c0];
                float v3 = acc[nt][3] + bch[c0 + 1];
                if (ch == 0) {
                    qa[nt >> 1][(nt & 1) * 2]     = pack2(v0, v1);
                    qa[nt >> 1][(nt & 1) * 2 + 1] = pack2(v2, v3);
                } else if (ch == 1) {
                    stu(kb + nq * KHSZ + r0 * QSTR + d0, pack2(v0, v1));
                    if (r0 + 8 < 56)
                        stu(kb + nq * KHSZ + (r0 + 8) * QSTR + d0, pack2(v2, v3));
                } else {
                    stu(vb + nq * VHSZ + r0 * QSTR + d0, pack2(v0, v1));
                    if (r0 + 8 < 56)
                        stu(vb + nq * VHSZ + (r0 + 8) * QSTR + d0, pack2(v2, v3));
                }
            }
        }
        __syncthreads();

        // ---- Phase C: fused attention (warp = head nq, rows mi*16..+15) ----
        {
            const int h = nq;
            const __half* kh = kb + h * KHSZ;
            const __half* vh = vb + h * VHSZ;
            const float* bmw = g_bm + (size_t)(w & 63) * (4 * 49 * 56) + h * (49 * 56);

            const uint32_t bK  = smem_u32(kh + lrB * QSTR + lkB);
            const uint32_t bK2 = smem_u32(kh + (48 + (lane & 7)) * QSTR + (lane & 8));
            const uint32_t bVt = smem_u32(vh + lrA * QSTR + lkA);   // trans: rows=tokens

            float acc[7][4];
#pragma unroll
            for (int i = 0; i < 7; i++)
#pragma unroll
                for (int j = 0; j < 4; j++) acc[i][j] = 0.f;

#pragma unroll
            for (int ks = 0; ks < 2; ks++) {
                const uint32_t ka = ks * 32;
                uint32_t k01[4], k23[4], k45[4], k6[2];
                ldsm4(k01, bK + ka);
                ldsm4(k23, bK + 16 * QSTR * 2 + ka);
                ldsm4(k45, bK + 32 * QSTR * 2 + ka);
                ldsm2(k6,  bK2 + ka);
                mma16(acc[0], qa[ks], k01[0], k01[1]);
                mma16(acc[1], qa[ks], k01[2], k01[3]);
                mma16(acc[2], qa[ks], k23[0], k23[1]);
                mma16(acc[3], qa[ks], k23[2], k23[3]);
                mma16(acc[4], qa[ks], k45[0], k45[1]);
                mma16(acc[5], qa[ks], k45[2], k45[3]);
                mma16(acc[6], qa[ks], k6[0],  k6[1]);
            }

            const float* bmA = bmw + (r0 < 49 ? r0 : 0) * 56;
            const float* bmB = bmw + (r0 + 8 < 49 ? r0 + 8 : 0) * 56;
#pragma unroll
            for (int nt = 0; nt < 7; nt++) {
                float2 bA = *(const float2*)(bmA + nt * 8 + 2 * t);
                float2 bB = *(const float2*)(bmB + nt * 8 + 2 * t);
                acc[nt][0] += bA.x; acc[nt][1] += bA.y;
                acc[nt][2] += bB.x; acc[nt][3] += bB.y;
            }
            if (t > 0) { acc[6][0] = -1e30f; acc[6][2] = -1e30f; }
            acc[6][1] = -1e30f; acc[6][3] = -1e30f;

            float mA = -1e30f, mB = -1e30f;
#pragma unroll
            for (int nt = 0; nt < 7; nt++) {
                mA = fmaxf(mA, fmaxf(acc[nt][0], acc[nt][1]));
                mB = fmaxf(mB, fmaxf(acc[nt][2], acc[nt][3]));
            }
            mA = fmaxf(mA, __shfl_xor_sync(0xffffffffu, mA, 1));
            mA = fmaxf(mA, __shfl_xor_sync(0xffffffffu, mA, 2));
            mB = fmaxf(mB, __shfl_xor_sync(0xffffffffu, mB, 1));
            mB = fmaxf(mB, __shfl_xor_sync(0xffffffffu, mB, 2));

            float sA = 0.f, sB = 0.f;
#pragma unroll
            for (int nt = 0; nt < 7; nt++) {
                acc[nt][0] = __expf(acc[nt][0] - mA); sA += acc[nt][0];
                acc[nt][1] = __expf(acc[nt][1] - mA); sA += acc[nt][1];
                acc[nt][2] = __expf(acc[nt][2] - mB); sB += acc[nt][2];
                acc[nt][3] = __expf(acc[nt][3] - mB); sB += acc[nt][3];
            }
            sA += __shfl_xor_sync(0xffffffffu, sA, 1);
            sA += __shfl_xor_sync(0xffffffffu, sA, 2);
            sB += __shfl_xor_sync(0xffffffffu, sB, 1);
            sB += __shfl_xor_sync(0xffffffffu, sB, 2);
            const float invA = 1.0f / sA, invB = 1.0f / sB;

            uint32_t pa[4][4];
#pragma unroll
            for (int ks = 0; ks < 4; ks++) {
                const int nt0 = 2 * ks, nt1 = 2 * ks + 1;
                pa[ks][0] = pack2(acc[nt0][0] * invA, acc[nt0][1] * invA);
                pa[ks][1] = pack2(acc[nt0][2] * invB, acc[nt0][3] * invB);
                pa[ks][2] = (nt1 < 7) ? pack2(acc[nt1][0] * invA, acc[nt1][1] * invA) : 0u;
                pa[ks][3] = (nt1 < 7) ? pack2(acc[nt1][2] * invB, acc[nt1][3] * invB) : 0u;
            }

            float o[4][4];
#pragma unroll
            for (int i = 0; i < 4; i++)
#pragma unroll
                for (int j = 0; j < 4; j++) o[i][j] = 0.f;
#pragma unroll
            for (int ks = 0; ks < 4; ks++) {
                // rows = tokens ks*16..+15 (56..63 are zero), trans -> B frags
                uint32_t v01[4], v23[4];
                ldsm4t(v01, bVt + ks * (16 * QSTR * 2));        // d 0..15
                ldsm4t(v23, bVt + ks * (16 * QSTR * 2) + 32);   // d 16..31
                mma16(o[0], pa[ks], v01[0], v01[1]);
                mma16(o[1], pa[ks], v01[2], v01[3]);
                mma16(o[2], pa[ks], v23[0], v23[1]);
                mma16(o[3], pa[ks], v23[2], v23[3]);
            }

#pragma unroll
            for (int nt = 0; nt < 4; nt++) {
                const int cb = h * 32 + nt * 8 + 2 * t;
                stu(xs + r0 * WSTR + cb,       pack2(o[nt][0], o[nt][1]));
                stu(xs + (r0 + 8) * WSTR + cb, pack2(o[nt][2], o[nt][3]));
            }
        }
        __syncthreads();

        // ---- Phase D: proj GEMM + direct global store ----
        {
            float acc[4][4];
#pragma unroll
            for (int i = 0; i < 4; i++)
#pragma unroll
                for (int j = 0; j < 4; j++) acc[i][j] = 0.f;

            const uint32_t bC0 = bW + 3 * (CHH * 2);
            const uint32_t bC1 = bC0 + 16 * WSTR * 2;
#pragma unroll
            for (int ks = 0; ks < 8; ks++) {
                uint32_t a0[4], q0[4], q1[4];
                ldsm4(a0, aX + ks * 32);
                ldsm4(q0, bC0 + ks * 32);
                ldsm4(q1, bC1 + ks * 32);
                mma16(acc[0], a0, q0[0], q0[1]);
                mma16(acc[1], a0, q0[2], q0[3]);
                mma16(acc[2], a0, q1[0], q1[1]);
                mma16(acc[3], a0, q1[2], q1[3]);
            }

            float* op = out + (size_t)w * (NTOK * CDIM);
#pragma unroll
            for (int nt = 0; nt < 4; nt++) {
                const int c0 = nq * 32 + nt * 8 + 2 * t;
                if (r0 < NTOK) {
                    float2 v = make_float2(acc[nt][0] + sb[384 + c0],
                                           acc[nt][1] + sb[384 + c0 + 1]);
                    *(float2*)(op + r0 * CDIM + c0) = v;
                }
                if (r0 + 8 < NTOK) {
                    float2 v = make_float2(acc[nt][2] + sb[384 + c0],
                                           acc[nt][3] + sb[384 + c0 + 1]);
                    *(float2*)(op + (r0 + 8) * CDIM + c0) = v;
                }
            }
        }
        // loop-top __syncthreads protects xs/kb/vb reuse
    }
}

extern "C" void kernel_launch(void* const* d_in, const int* in_sizes, int n_in,
                              void* d_out, int out_size)
{
    const float* x          = (const float*)d_in[0];
    const float* mask       = (const float*)d_in[1];
    const float* qkv_w      = (const float*)d_in[2];
    const float* qkv_b      = (const float*)d_in[3];
    const float* proj_w     = (const float*)d_in[4];
    const float* proj_b     = (const float*)d_in[5];
    const float* bias_table = (const float*)d_in[6];
    float* out = (float*)d_out;

    const int NW = in_sizes[0] / (NTOK * CDIM);   // 8192 windows

    prep_all<<<(BM_N + 66048 + 255) / 256, 256>>>(qkv_w, qkv_b, proj_w, proj_b, mask, bias_table);

    int sms = 0;
    cudaDeviceGetAttribute(&sms, cudaDevAttrMultiProcessorCount, 0);
    if (sms <= 0) sms = 148;
    int grid = (sms < NW) ? sms : NW;

    cudaFuncSetAttribute(wattn, cudaFuncAttributeMaxDynamicSharedMemorySize, SMEM_BYTES);
    wattn<<<grid, THREADS, SMEM_BYTES>>>(x, out, NW);
}